// round 2
// baseline (speedup 1.0000x reference)
#include <cuda_runtime.h>
#include <math.h>

// ---------------- problem constants ----------------
#define RAYS    1024
#define NCO     64
#define NFI     32
#define NAGG    96
#define MIND    0.035f
#define MAXD    35.0f
#define DD      90
#define NHEADS  12
#define DHD     64
#define INNERD  768
#define MLPD    1536
#define KVD     768
#define PTOK    128
#define LDH     100     // smem row stride for 90-wide tensors (4 mod 32 -> conflict-free LN)
#define LDSS    132     // smem row stride for 128-wide tensors
#define PPB     16      // points per block (2 warps x 8 points)

// ---------------- device scratch (no allocs allowed) ----------------
__device__ float g_kt   [2*NHEADS*DHD*PTOK];   // [layer][head][d][key]
__device__ float g_vv   [2*NHEADS*PTOK*DHD];   // [layer][head][key][d]
__device__ float g_dens_c[RAYS*NCO];
__device__ float g_col_c [RAYS*NCO*3];
__device__ float g_dens_f[RAYS*NAGG];
__device__ float g_col_f [RAYS*NAGG*3];
__device__ float g_depths[RAYS*NAGG];

struct NetP {
    const float *x, *rays;
    const float *ln1w, *ln1b, *wq, *wo, *bo, *ln2w, *ln2b, *w1, *b1, *w2, *b2;
    const float *wc1, *bc1, *wc2, *bc2, *wd1, *bd1, *wd2, *bd2;
};

__device__ __forceinline__ float coarse_depth(int s) {
    const float step = (MAXD - MIND) / 64.0f;
    float b0 = MIND + s * step;
    float b1 = MIND + (s + 1) * step;
    return 0.5f * (b0 + b1);
}

// ---------------- KV precompute: kv = z @ wkv, scattered to kt/v ----------------
__global__ void kv_kernel(const float* __restrict__ z, const float* __restrict__ wkv) {
    int e = blockIdx.x * blockDim.x + threadIdx.x;
    if (e >= 2 * PTOK * 2 * INNERD) return;
    int layer = e / (PTOK * 2 * INNERD);
    int rem   = e - layer * (PTOK * 2 * INNERD);
    int p   = rem / (2 * INNERD);
    int col = rem - p * (2 * INNERD);
    const float* zr = z + p * KVD;
    const float* wc = wkv + layer * KVD * 2 * INNERD + col;
    float acc = 0.f;
#pragma unroll 8
    for (int k = 0; k < KVD; k++) acc = fmaf(zr[k], wc[k * 2 * INNERD], acc);
    int head = col >> 7, c = col & 127;
    if (c < DHD) g_kt[((layer * NHEADS + head) * DHD + c) * PTOK + p] = acc;
    else         g_vv[((layer * NHEADS + head) * PTOK + p) * DHD + (c - DHD)] = acc;
}

// ---------------- register-tiled GEMM: out[rows of this warp][NO] = in_smem @ W[NI][NO] ----
// warp w owns points w*8..w*8+7 (broadcast LDS); lane l owns output cols l+32*j.
template <int NI, int NOJ, int NO, int LDIN, class Epi>
__device__ __forceinline__ void gemm_tile(const float* __restrict__ in,
                                          const float* __restrict__ W,
                                          int ldw, Epi epi) {
    const int l  = threadIdx.x & 31;
    const int wp = threadIdx.x >> 5;
    float acc[8][NOJ];
#pragma unroll
    for (int i = 0; i < 8; i++)
#pragma unroll
        for (int j = 0; j < NOJ; j++) acc[i][j] = 0.f;
    const float* inb = in + wp * 8 * LDIN;
    int ni = 0;
#pragma unroll 4
    for (; ni + 4 <= NI; ni += 4) {
        float4 a[8];
#pragma unroll
        for (int i = 0; i < 8; i++)
            a[i] = *reinterpret_cast<const float4*>(inb + i * LDIN + ni);
#pragma unroll
        for (int k = 0; k < 4; k++) {
            float wv[NOJ];
#pragma unroll
            for (int j = 0; j < NOJ; j++) {
                int o = l + 32 * j;
                wv[j] = ((NO & 31) == 0 || o < NO) ? W[(ni + k) * ldw + o] : 0.f;
            }
#pragma unroll
            for (int i = 0; i < 8; i++) {
                float av = (k == 0) ? a[i].x : (k == 1) ? a[i].y : (k == 2) ? a[i].z : a[i].w;
#pragma unroll
                for (int j = 0; j < NOJ; j++) acc[i][j] = fmaf(av, wv[j], acc[i][j]);
            }
        }
    }
    for (; ni < NI; ni++) {
        float wv[NOJ];
#pragma unroll
        for (int j = 0; j < NOJ; j++) {
            int o = l + 32 * j;
            wv[j] = ((NO & 31) == 0 || o < NO) ? W[ni * ldw + o] : 0.f;
        }
#pragma unroll
        for (int i = 0; i < 8; i++) {
            float av = inb[i * LDIN + ni];
#pragma unroll
            for (int j = 0; j < NOJ; j++) acc[i][j] = fmaf(av, wv[j], acc[i][j]);
        }
    }
#pragma unroll
    for (int i = 0; i < 8; i++)
#pragma unroll
        for (int j = 0; j < NOJ; j++) {
            int o = l + 32 * j;
            if ((NO & 31) == 0 || o < NO) epi(wp * 8 + i, o, acc[i][j]);
        }
}

// Warp-local LayerNorm over 90 features of this warp's 8 rows; 4 lanes per point.
__device__ __forceinline__ void ln_warp(const float* __restrict__ src, float* __restrict__ dst,
                                        const float* __restrict__ w, const float* __restrict__ b) {
    const int l  = threadIdx.x & 31;
    const int wp = threadIdx.x >> 5;
    const int pl = l >> 2, sub = l & 3;
    const float* row = src + (wp * 8 + pl) * LDH;
    float s = 0.f;
    for (int f = sub; f < DD; f += 4) s += row[f];
    s += __shfl_xor_sync(0xffffffffu, s, 1);
    s += __shfl_xor_sync(0xffffffffu, s, 2);
    float m = s * (1.0f / DD);
    float v = 0.f;
    for (int f = sub; f < DD; f += 4) { float d = row[f] - m; v += d * d; }
    v += __shfl_xor_sync(0xffffffffu, v, 1);
    v += __shfl_xor_sync(0xffffffffu, v, 2);
    float inv = 1.0f / sqrtf(v * (1.0f / DD) + 1e-5f);
    float* drow = dst + (wp * 8 + pl) * LDH;
    for (int f = sub; f < DD; f += 4) drow[f] = (row[f] - m) * inv * w[f] + b[f];
    __syncwarp();
}

// ---------------- fused NeRF network: 16 points / block, fully warp-synchronous ----
__global__ void __launch_bounds__(64) net_kernel(NetP P, int mode /*0 coarse, 1 fine*/) {
    __shared__ float sh_h [PPB * LDH];   // 1600
    __shared__ float sh_hn[PPB * LDH];   // 1600
    __shared__ float sh_q [PPB * 64];    // 1024
    __shared__ float sh_s [PPB * LDSS];  // 2112
    __shared__ float sh_o [PPB * 64];    // 1024

    const int t  = threadIdx.x;
    const int l  = t & 31;
    const int wp = t >> 5;
    const int pl = l >> 2, sub = l & 3;   // 4 lanes per point
    const int base = blockIdx.x * PPB;
    const int S = mode ? NAGG : NCO;

    // ---- coords (per warp: 8 points x 3 dims = 24 lanes) ----
    if (l < 24) {
        int p = l / 3, d = l - (l / 3) * 3;
        int gp = base + wp * 8 + p;
        int r = gp / S, s = gp - r * S;
        float depth = mode ? g_depths[r * NAGG + s] : coarse_depth(s);
        sh_o[(wp * 8 + p) * 64 + d] = P.x[r * 3 + d] + P.rays[r * 3 + d] * depth;
    }
    __syncwarp();
    // ---- positional encoding: [sin(3x15) | cos(3x15)] ----
    for (int idx = l; idx < 8 * DD; idx += 32) {
        int p = idx / DD, f = idx - p * DD;
        int bb = (f < 45) ? f : f - 45;
        int dim = bb / 15, oct = bb - dim * 15;
        float arg = sh_o[(wp * 8 + p) * 64 + dim] * (3.14159265358979323846f * (float)(1 << oct));
        sh_h[(wp * 8 + p) * LDH + f] = (f < 45) ? sinf(arg) : cosf(arg);
    }
    __syncwarp();

    for (int layer = 0; layer < 2; layer++) {
        // ---- LN1 + attention ----
        ln_warp(sh_h, sh_hn, P.ln1w + layer * DD, P.ln1b + layer * DD);
        {
            float accwo[8][3];
#pragma unroll
            for (int i = 0; i < 8; i++)
#pragma unroll
                for (int j = 0; j < 3; j++) accwo[i][j] = 0.f;
            for (int head = 0; head < NHEADS; head++) {
                gemm_tile<DD, 2, DHD, LDH>(sh_hn, P.wq + layer * DD * INNERD + head * DHD, INNERD,
                    [&](int p, int o, float v) { sh_q[p * DHD + o] = v; });
                __syncwarp();
                gemm_tile<DHD, 4, PTOK, DHD>(sh_q, g_kt + (layer * NHEADS + head) * DHD * PTOK, PTOK,
                    [&](int p, int o, float v) { sh_s[p * LDSS + o] = v * 0.125f; });
                __syncwarp();
                // ---- softmax over 128 keys: 4 lanes / point, elems e = sub + 4k ----
                {
                    float* row = sh_s + (wp * 8 + pl) * LDSS;
                    float mx = row[sub];
#pragma unroll
                    for (int k = 1; k < 32; k++) mx = fmaxf(mx, row[sub + 4 * k]);
                    mx = fmaxf(mx, __shfl_xor_sync(0xffffffffu, mx, 1));
                    mx = fmaxf(mx, __shfl_xor_sync(0xffffffffu, mx, 2));
                    float ps = 0.f;
#pragma unroll
                    for (int k = 0; k < 32; k++) {
                        float v = expf(row[sub + 4 * k] - mx);
                        row[sub + 4 * k] = v;
                        ps += v;
                    }
                    ps += __shfl_xor_sync(0xffffffffu, ps, 1);
                    ps += __shfl_xor_sync(0xffffffffu, ps, 2);
                    float inv = 1.0f / ps;
#pragma unroll
                    for (int k = 0; k < 32; k++) row[sub + 4 * k] *= inv;
                }
                __syncwarp();
                gemm_tile<PTOK, 2, DHD, LDSS>(sh_s, g_vv + (layer * NHEADS + head) * PTOK * DHD, DHD,
                    [&](int p, int o, float v) { sh_o[p * DHD + o] = v; });
                __syncwarp();
                gemm_tile<DHD, 3, DD, DHD>(sh_o, P.wo + layer * INNERD * DD + head * DHD * DD, DD,
                    [&](int p, int o, float v) { accwo[p & 7][o >> 5] += v; });
                __syncwarp();
            }
            const float* bo = P.bo + layer * DD;
#pragma unroll
            for (int i = 0; i < 8; i++)
#pragma unroll
                for (int j = 0; j < 3; j++) {
                    int o = l + 32 * j;
                    if (o < DD) sh_h[(wp * 8 + i) * LDH + o] += accwo[i][j] + bo[o];
                }
            __syncwarp();
        }
        // ---- LN2 + MLP ----
        ln_warp(sh_h, sh_hn, P.ln2w + layer * DD, P.ln2b + layer * DD);
        {
            float accw2[8][3];
#pragma unroll
            for (int i = 0; i < 8; i++)
#pragma unroll
                for (int j = 0; j < 3; j++) accw2[i][j] = 0.f;
            for (int c = 0; c < MLPD / 128; c++) {
                const float* b1c = P.b1 + layer * MLPD + c * 128;
                gemm_tile<DD, 4, 128, LDH>(sh_hn, P.w1 + layer * DD * MLPD + c * 128, MLPD,
                    [&](int p, int o, float v) {
                        float xx = v + b1c[o];
                        sh_s[p * LDSS + o] = 0.5f * xx * (1.0f + erff(xx * 0.70710678118654752f));
                    });
                __syncwarp();
                gemm_tile<128, 3, DD, LDSS>(sh_s, P.w2 + layer * MLPD * DD + c * 128 * DD, DD,
                    [&](int p, int o, float v) { accw2[p & 7][o >> 5] += v; });
                __syncwarp();
            }
            const float* b2 = P.b2 + layer * DD;
#pragma unroll
            for (int i = 0; i < 8; i++)
#pragma unroll
                for (int j = 0; j < 3; j++) {
                    int o = l + 32 * j;
                    if (o < DD) sh_h[(wp * 8 + i) * LDH + o] += accw2[i][j] + b2[o];
                }
            __syncwarp();
        }
    }

    // ---- density head ----
    gemm_tile<DD, 4, 128, LDH>(sh_h, P.wd1, 128,
        [&](int p, int o, float v) { sh_s[p * LDSS + o] = fmaxf(v + P.bd1[o], 0.f); });
    __syncwarp();
    {
        const float* row = sh_s + (wp * 8 + pl) * LDSS;
        float a = 0.f;
#pragma unroll
        for (int k = 0; k < 32; k++) a = fmaf(row[sub + 4 * k], P.wd2[sub + 4 * k], a);
        a += __shfl_xor_sync(0xffffffffu, a, 1);
        a += __shfl_xor_sync(0xffffffffu, a, 2);
        if (sub == 0) {
            a += P.bd2[0];
            float sp = fmaxf(a, 0.f) + log1pf(expf(-fabsf(a)));   // softplus
            float* dst = mode ? g_dens_f : g_dens_c;
            dst[base + wp * 8 + pl] = sp;
        }
    }
    __syncwarp();
    // ---- color head ----
    gemm_tile<DD, 4, 128, LDH>(sh_h, P.wc1, 128,
        [&](int p, int o, float v) { sh_s[p * LDSS + o] = fmaxf(v + P.bc1[o], 0.f); });
    __syncwarp();
    {
        const float* row = sh_s + (wp * 8 + pl) * LDSS;
        float c0 = 0.f, c1 = 0.f, c2 = 0.f;
#pragma unroll
        for (int k = 0; k < 32; k++) {
            float v = row[sub + 4 * k];
            const float* wr = P.wc2 + (sub + 4 * k) * 3;
            c0 = fmaf(v, wr[0], c0);
            c1 = fmaf(v, wr[1], c1);
            c2 = fmaf(v, wr[2], c2);
        }
        c0 += __shfl_xor_sync(0xffffffffu, c0, 1);
        c0 += __shfl_xor_sync(0xffffffffu, c0, 2);
        c1 += __shfl_xor_sync(0xffffffffu, c1, 1);
        c1 += __shfl_xor_sync(0xffffffffu, c1, 2);
        c2 += __shfl_xor_sync(0xffffffffu, c2, 1);
        c2 += __shfl_xor_sync(0xffffffffu, c2, 2);
        if (sub == 0) {
            int gp = base + wp * 8 + pl;
            float* dst = mode ? g_col_f : g_col_c;
            dst[gp * 3 + 0] = 1.0f / (1.0f + expf(-(c0 + P.bc2[0])));
            dst[gp * 3 + 1] = 1.0f / (1.0f + expf(-(c1 + P.bc2[1])));
            dst[gp * 3 + 2] = 1.0f / (1.0f + expf(-(c2 + P.bc2[2])));
        }
    }
}

// ---------------- coarse render + PDF resampling + merge ----------------
__global__ void coarse_post_kernel(float* __restrict__ out) {
    int r = blockIdx.x * blockDim.x + threadIdx.x;
    if (r >= RAYS) return;
    float cd[NCO];
    for (int s = 0; s < NCO; s++) cd[s] = coarse_depth(s);

    float w[NCO];
    float T = 1.f, acc = 0.f, rgb0 = 0.f, rgb1 = 0.f, rgb2 = 0.f, dsum = 0.f;
    for (int s = 0; s < NCO; s++) {
        float seg = (s < NCO - 1) ? cd[s + 1] - cd[s] : 1e10f;
        float dens = g_dens_c[r * NCO + s];
        float alpha = 1.0f - expf(-dens * seg);
        float wi = alpha * T;
        w[s] = wi;
        T *= (1.0f - alpha + 1e-10f);
        acc += wi;
        rgb0 += wi * g_col_c[(r * NCO + s) * 3 + 0];
        rgb1 += wi * g_col_c[(r * NCO + s) * 3 + 1];
        rgb2 += wi * g_col_c[(r * NCO + s) * 3 + 2];
        dsum += wi * cd[s];
    }
    float inv = 1.0f / (acc + 1e-8f);
    out[3072 + r * 3 + 0] = 1.0f - acc + (rgb0 * inv) * acc;
    out[3072 + r * 3 + 1] = 1.0f - acc + (rgb1 * inv) * acc;
    out[3072 + r * 3 + 2] = 1.0f - acc + (rgb2 * inv) * acc;
    out[7168 + r] = dsum * inv;

    // ---- sample_pdf: bins = mids(63), weights = w[1..62] ----
    float bins[63], cdf[63];
    for (int i = 0; i < 63; i++) bins[i] = 0.5f * (cd[i] + cd[i + 1]);
    float wsum = 0.f;
    for (int i = 0; i < 62; i++) wsum += w[i + 1] + 1e-5f;
    cdf[0] = 0.f;
    float c0 = 0.f;
    for (int i = 0; i < 62; i++) { c0 += (w[i + 1] + 1e-5f) / wsum; cdf[i + 1] = c0; }

    float fd[NFI];
    for (int j = 0; j < NFI; j++) {
        float u = (j + 0.5f) * (1.0f / NFI);
        int ind = 0;
        for (int k = 0; k < 63; k++) if (cdf[k] <= u) ind = k + 1;   // searchsorted right
        int below = ind - 1; if (below < 0) below = 0; if (below > 62) below = 62;
        int above = ind;     if (above > 62) above = 62;
        float cb = cdf[below], ca = cdf[above];
        float bb = bins[below], ba = bins[above];
        float denom = ca - cb;
        if (denom < 1e-5f) denom = 1.0f;
        fd[j] = bb + (u - cb) / denom * (ba - bb);
    }
    // ---- stable merge (coarse first on ties) == stable argsort of concat ----
    int i = 0, j = 0;
    for (int k = 0; k < NAGG; k++) {
        float v;
        if (j >= NFI || (i < NCO && cd[i] <= fd[j])) v = cd[i++];
        else v = fd[j++];
        g_depths[r * NAGG + k] = v;
    }
}

// ---------------- fine render ----------------
__global__ void fine_post_kernel(float* __restrict__ out) {
    int r = blockIdx.x * blockDim.x + threadIdx.x;
    if (r >= RAYS) return;
    float d[NAGG];
    for (int s = 0; s < NAGG; s++) d[s] = g_depths[r * NAGG + s];
    float T = 1.f, acc = 0.f, rgb0 = 0.f, rgb1 = 0.f, rgb2 = 0.f, dsum = 0.f;
    for (int s = 0; s < NAGG; s++) {
        float seg = (s < NAGG - 1) ? d[s + 1] - d[s] : 1e10f;
        float dens = g_dens_f[r * NAGG + s];
        float alpha = 1.0f - expf(-dens * seg);
        float wi = alpha * T;
        T *= (1.0f - alpha + 1e-10f);
        acc += wi;
        rgb0 += wi * g_col_f[(r * NAGG + s) * 3 + 0];
        rgb1 += wi * g_col_f[(r * NAGG + s) * 3 + 1];
        rgb2 += wi * g_col_f[(r * NAGG + s) * 3 + 2];
        dsum += wi * d[s];
    }
    float inv = 1.0f / (acc + 1e-8f);
    out[r * 3 + 0] = 1.0f - acc + (rgb0 * inv) * acc;
    out[r * 3 + 1] = 1.0f - acc + (rgb1 * inv) * acc;
    out[r * 3 + 2] = 1.0f - acc + (rgb2 * inv) * acc;
    out[6144 + r] = dsum * inv;
}

// ---------------- launch ----------------
extern "C" void kernel_launch(void* const* d_in, const int* in_sizes, int n_in,
                              void* d_out, int out_size) {
    const float* z    = (const float*)d_in[0];
    const float* x    = (const float*)d_in[1];
    const float* rays = (const float*)d_in[2];
    NetP P;
    P.x = x; P.rays = rays;
    P.ln1w = (const float*)d_in[3];
    P.ln1b = (const float*)d_in[4];
    P.wq   = (const float*)d_in[5];
    const float* wkv = (const float*)d_in[6];
    P.wo   = (const float*)d_in[7];
    P.bo   = (const float*)d_in[8];
    P.ln2w = (const float*)d_in[9];
    P.ln2b = (const float*)d_in[10];
    P.w1   = (const float*)d_in[11];
    P.b1   = (const float*)d_in[12];
    P.w2   = (const float*)d_in[13];
    P.b2   = (const float*)d_in[14];
    P.wc1  = (const float*)d_in[15];
    P.bc1  = (const float*)d_in[16];
    P.wc2  = (const float*)d_in[17];
    P.bc2  = (const float*)d_in[18];
    P.wd1  = (const float*)d_in[19];
    P.bd1  = (const float*)d_in[20];
    P.wd2  = (const float*)d_in[21];
    P.bd2  = (const float*)d_in[22];
    float* out = (float*)d_out;

    // 1) KV projection: 2 layers x 128 tokens x 1536 cols
    kv_kernel<<<(2 * PTOK * 2 * INNERD + 255) / 256, 256>>>(z, wkv);
    // 2) coarse network: 1024*64 points, 16 / block
    net_kernel<<<(RAYS * NCO) / PPB, 64>>>(P, 0);
    // 3) coarse render + fine sampling + merge
    coarse_post_kernel<<<(RAYS + 127) / 128, 128>>>(out);
    // 4) fine network: 1024*96 points
    net_kernel<<<(RAYS * NAGG) / PPB, 64>>>(P, 1);
    // 5) fine render
    fine_post_kernel<<<(RAYS + 127) / 128, 128>>>(out);
}

// round 3
// speedup vs baseline: 1.8042x; 1.8042x over previous
#include <cuda_runtime.h>
#include <math.h>

typedef unsigned long long ull;

// ---------------- problem constants ----------------
#define RAYS    1024
#define NCO     64
#define NFI     32
#define NAGG    96
#define MIND    0.035f
#define MAXD    35.0f
#define DD      90
#define NHEADS  12
#define DHD     64
#define INNERD  768
#define MLPD    1536
#define KVD     768
#define PTOK    128
#define LDH     100     // paired row stride 2*LDH=200 (== 8 mod 32 -> conflict-free)
#define LDSS    132     // paired row stride 2*LDSS=264 (== 8 mod 32)
#define PPB     16      // points per block (2 warps x 8 points = 4 pairs/warp)

// ---------------- device scratch ----------------
__device__ float g_kt   [2*NHEADS*DHD*PTOK];   // [layer][head][d][key]
__device__ float g_vv   [2*NHEADS*PTOK*DHD];   // [layer][head][key][d]
__device__ float g_dens_c[RAYS*NCO];
__device__ float g_col_c [RAYS*NCO*3];
__device__ float g_dens_f[RAYS*NAGG];
__device__ float g_col_f [RAYS*NAGG*3];
__device__ float g_depths[RAYS*NAGG];

struct NetP {
    const float *x, *rays;
    const float *ln1w, *ln1b, *wq, *wo, *bo, *ln2w, *ln2b, *w1, *b1, *w2, *b2;
    const float *wc1, *bc1, *wc2, *bc2, *wd1, *bd1, *wd2, *bd2;
};

__device__ __forceinline__ float coarse_depth(int s) {
    const float step = (MAXD - MIND) / 64.0f;
    return 0.5f * ((MIND + s * step) + (MIND + (s + 1) * step));
}

// ---------------- f32x2 helpers (Blackwell dual-fp32, exact fp32 semantics) ----
__device__ __forceinline__ ull pack2(float x, float y) {
    ull r; asm("mov.b64 %0, {%1, %2};" : "=l"(r) : "f"(x), "f"(y)); return r;
}
__device__ __forceinline__ ull pack2d(float x) { return pack2(x, x); }
__device__ __forceinline__ void ffma2(ull& d, ull a, ull b) {
    asm("fma.rn.f32x2 %0, %1, %2, %0;" : "+l"(d) : "l"(a), "l"(b));
}
__device__ __forceinline__ float2 unpack2(ull v) {
    float2 r; asm("mov.b64 {%0, %1}, %2;" : "=f"(r.x), "=f"(r.y) : "l"(v)); return r;
}

// paired activation layout: buf[(p>>1)*2*LD + 2*k + (p&1)]
#define PIDX(p, LD, k) (((p) >> 1) * (2 * (LD)) + 2 * (k) + ((p) & 1))

// ---------------- KV precompute ----------------
__global__ void kv_kernel(const float* __restrict__ z, const float* __restrict__ wkv) {
    int e = blockIdx.x * blockDim.x + threadIdx.x;
    if (e >= 2 * PTOK * 2 * INNERD) return;
    int layer = e / (PTOK * 2 * INNERD);
    int rem   = e - layer * (PTOK * 2 * INNERD);
    int p   = rem / (2 * INNERD);
    int col = rem - p * (2 * INNERD);
    const float* zr = z + p * KVD;
    const float* wc = wkv + layer * KVD * 2 * INNERD + col;
    float acc = 0.f;
#pragma unroll 8
    for (int k = 0; k < KVD; k++) acc = fmaf(zr[k], wc[k * 2 * INNERD], acc);
    int head = col >> 7, c = col & 127;
    if (c < DHD) g_kt[((layer * NHEADS + head) * DHD + c) * PTOK + p] = acc;
    else         g_vv[((layer * NHEADS + head) * PTOK + p) * DHD + (c - DHD)] = acc;
}

// ---------------- FFMA2 register-tiled GEMM -------------------------------
// Input is PAIRED smem. Warp owns 4 point-pairs (8 points). Lane owns:
//   WMODE==1 (vector weights): cols NCOL*l + j  (NCOL in {2,4}), NO == 32*NCOL
//   WMODE==0 (strided):        cols l + 32*j, masked at NO
// acc[i][j] holds a packed (pt 2i, pt 2i+1) pair. Accumulation order over k
// identical to the scalar version -> bit-identical fp32 results.
template <int NI, int NCOL, int LDIN, int WMODE, int NO, class Epi>
__device__ __forceinline__ void gemm2(const float* __restrict__ in,
                                      const float* __restrict__ W,
                                      const int ldw, Epi epi) {
    const int l  = threadIdx.x & 31;
    const int wp = threadIdx.x >> 5;
    ull acc[4][NCOL];
#pragma unroll
    for (int i = 0; i < 4; i++)
#pragma unroll
        for (int j = 0; j < NCOL; j++) acc[i][j] = 0ull;

    const float* inb = in + (wp * 4) * (2 * LDIN);
    int ni = 0;
#pragma unroll 2
    for (; ni + 4 <= NI; ni += 4) {
        ull a[4][4];
#pragma unroll
        for (int i = 0; i < 4; i++) {
            ulonglong2 t0 = *reinterpret_cast<const ulonglong2*>(inb + i * 2 * LDIN + 2 * ni);
            ulonglong2 t1 = *reinterpret_cast<const ulonglong2*>(inb + i * 2 * LDIN + 2 * ni + 4);
            a[i][0] = t0.x; a[i][1] = t0.y; a[i][2] = t1.x; a[i][3] = t1.y;
        }
#pragma unroll
        for (int k = 0; k < 4; k++) {
            ull wv[NCOL];
            if (WMODE == 1) {
                if (NCOL == 4) {
                    float4 w4 = *reinterpret_cast<const float4*>(W + (ni + k) * ldw + 4 * l);
                    wv[0] = pack2d(w4.x); wv[1] = pack2d(w4.y);
                    wv[2] = pack2d(w4.z); wv[3] = pack2d(w4.w);
                } else {
                    float2 w2 = *reinterpret_cast<const float2*>(W + (ni + k) * ldw + 2 * l);
                    wv[0] = pack2d(w2.x); wv[1] = pack2d(w2.y);
                }
            } else {
#pragma unroll
                for (int j = 0; j < NCOL; j++) {
                    int o = l + 32 * j;
                    float w = (o < NO) ? W[(ni + k) * ldw + o] : 0.f;
                    wv[j] = pack2d(w);
                }
            }
#pragma unroll
            for (int i = 0; i < 4; i++)
#pragma unroll
                for (int j = 0; j < NCOL; j++) ffma2(acc[i][j], a[i][k], wv[j]);
        }
    }
    if (NI & 2) {   // remainder of 2 (NI=90)
        ull a[4][2];
#pragma unroll
        for (int i = 0; i < 4; i++) {
            ulonglong2 t0 = *reinterpret_cast<const ulonglong2*>(inb + i * 2 * LDIN + 2 * ni);
            a[i][0] = t0.x; a[i][1] = t0.y;
        }
#pragma unroll
        for (int k = 0; k < 2; k++) {
            ull wv[NCOL];
            if (WMODE == 1) {
                if (NCOL == 4) {
                    float4 w4 = *reinterpret_cast<const float4*>(W + (ni + k) * ldw + 4 * l);
                    wv[0] = pack2d(w4.x); wv[1] = pack2d(w4.y);
                    wv[2] = pack2d(w4.z); wv[3] = pack2d(w4.w);
                } else {
                    float2 w2 = *reinterpret_cast<const float2*>(W + (ni + k) * ldw + 2 * l);
                    wv[0] = pack2d(w2.x); wv[1] = pack2d(w2.y);
                }
            } else {
#pragma unroll
                for (int j = 0; j < NCOL; j++) {
                    int o = l + 32 * j;
                    float w = (o < NO) ? W[(ni + k) * ldw + o] : 0.f;
                    wv[j] = pack2d(w);
                }
            }
#pragma unroll
            for (int i = 0; i < 4; i++)
#pragma unroll
                for (int j = 0; j < NCOL; j++) ffma2(acc[i][j], a[i][k], wv[j]);
        }
    }
#pragma unroll
    for (int i = 0; i < 4; i++)
#pragma unroll
        for (int j = 0; j < NCOL; j++) {
            int o = (WMODE == 1) ? (NCOL * l + j) : (l + 32 * j);
            if (WMODE == 1 || o < NO) epi(wp * 4 + i, o, unpack2(acc[i][j]));
        }
}

// Warp-local LayerNorm on paired layout; 4 lanes per point.
__device__ __forceinline__ void ln_warp(const float* __restrict__ src, float* __restrict__ dst,
                                        const float* __restrict__ w, const float* __restrict__ b) {
    const int l  = threadIdx.x & 31;
    const int wp = threadIdx.x >> 5;
    const int pl = l >> 2, sub = l & 3;
    const int pt = wp * 8 + pl;
    const float* rowb = src + ((pt >> 1) * (2 * LDH) + (pt & 1));
    float s = 0.f;
    for (int f = sub; f < DD; f += 4) s += rowb[2 * f];
    s += __shfl_xor_sync(0xffffffffu, s, 1);
    s += __shfl_xor_sync(0xffffffffu, s, 2);
    float m = s * (1.0f / DD);
    float v = 0.f;
    for (int f = sub; f < DD; f += 4) { float d = rowb[2 * f] - m; v += d * d; }
    v += __shfl_xor_sync(0xffffffffu, v, 1);
    v += __shfl_xor_sync(0xffffffffu, v, 2);
    float inv = 1.0f / sqrtf(v * (1.0f / DD) + 1e-5f);
    float* drow = dst + ((pt >> 1) * (2 * LDH) + (pt & 1));
    for (int f = sub; f < DD; f += 4) drow[2 * f] = (rowb[2 * f] - m) * inv * w[f] + b[f];
    __syncwarp();
}

// ---------------- fused NeRF network ----------------
__global__ void __launch_bounds__(64) net_kernel(NetP P, int mode /*0 coarse, 1 fine*/) {
    __shared__ __align__(16) float sh_h [(PPB / 2) * 2 * LDH ];  // 1600
    __shared__ __align__(16) float sh_hn[(PPB / 2) * 2 * LDH ];  // 1600
    __shared__ __align__(16) float sh_q [(PPB / 2) * 2 * DHD ];  // 1024
    __shared__ __align__(16) float sh_s [(PPB / 2) * 2 * LDSS];  // 2112
    __shared__ __align__(16) float sh_o [(PPB / 2) * 2 * DHD ];  // 1024

    const int t  = threadIdx.x;
    const int l  = t & 31;
    const int wp = t >> 5;
    const int pl = l >> 2, sub = l & 3;
    const int base = blockIdx.x * PPB;
    const int S = mode ? NAGG : NCO;

    // ---- coords (temp in sh_q, consumed by posenc before wq uses sh_q) ----
    if (l < 24) {
        int p = l / 3, d = l - (l / 3) * 3;
        int gp = base + wp * 8 + p;
        int r = gp / S, s = gp - r * S;
        float depth = mode ? g_depths[r * NAGG + s] : coarse_depth(s);
        sh_q[(wp * 8 + p) * 4 + d] = P.x[r * 3 + d] + P.rays[r * 3 + d] * depth;
    }
    __syncwarp();
    // ---- positional encoding ----
    for (int idx = l; idx < 8 * DD; idx += 32) {
        int p = idx / DD, f = idx - p * DD;
        int bb = (f < 45) ? f : f - 45;
        int dim = bb / 15, oct = bb - dim * 15;
        int pt = wp * 8 + p;
        float arg = sh_q[pt * 4 + dim] * (3.14159265358979323846f * (float)(1 << oct));
        sh_h[PIDX(pt, LDH, f)] = (f < 45) ? sinf(arg) : cosf(arg);
    }
    __syncwarp();

    for (int layer = 0; layer < 2; layer++) {
        // ---- LN1 + attention ----
        ln_warp(sh_h, sh_hn, P.ln1w + layer * DD, P.ln1b + layer * DD);
        {
            float2 accw[4][3];
#pragma unroll
            for (int i = 0; i < 4; i++)
#pragma unroll
                for (int j = 0; j < 3; j++) accw[i][j] = make_float2(0.f, 0.f);
            for (int head = 0; head < NHEADS; head++) {
                gemm2<DD, 2, LDH, 1, DHD>(sh_hn, P.wq + layer * DD * INNERD + head * DHD, INNERD,
                    [&](int pr, int o, float2 v) {
                        *reinterpret_cast<float2*>(&sh_q[pr * 2 * DHD + 2 * o]) = v;
                    });
                __syncwarp();
                gemm2<DHD, 4, DHD, 1, PTOK>(sh_q, g_kt + (layer * NHEADS + head) * DHD * PTOK, PTOK,
                    [&](int pr, int o, float2 v) {
                        v.x *= 0.125f; v.y *= 0.125f;
                        *reinterpret_cast<float2*>(&sh_s[pr * 2 * LDSS + 2 * o]) = v;
                    });
                __syncwarp();
                // ---- softmax over 128 keys: 4 lanes / point ----
                {
                    const int pt = wp * 8 + pl;
                    float* rowb = sh_s + ((pt >> 1) * 2 * LDSS + (pt & 1));
                    float mx = rowb[2 * sub];
#pragma unroll
                    for (int k = 1; k < 32; k++) mx = fmaxf(mx, rowb[2 * (sub + 4 * k)]);
                    mx = fmaxf(mx, __shfl_xor_sync(0xffffffffu, mx, 1));
                    mx = fmaxf(mx, __shfl_xor_sync(0xffffffffu, mx, 2));
                    float ps = 0.f;
#pragma unroll
                    for (int k = 0; k < 32; k++) {
                        float v = expf(rowb[2 * (sub + 4 * k)] - mx);
                        rowb[2 * (sub + 4 * k)] = v;
                        ps += v;
                    }
                    ps += __shfl_xor_sync(0xffffffffu, ps, 1);
                    ps += __shfl_xor_sync(0xffffffffu, ps, 2);
                    float inv = 1.0f / ps;
#pragma unroll
                    for (int k = 0; k < 32; k++) rowb[2 * (sub + 4 * k)] *= inv;
                }
                __syncwarp();
                gemm2<PTOK, 2, LDSS, 1, DHD>(sh_s, g_vv + (layer * NHEADS + head) * PTOK * DHD, DHD,
                    [&](int pr, int o, float2 v) {
                        *reinterpret_cast<float2*>(&sh_o[pr * 2 * DHD + 2 * o]) = v;
                    });
                __syncwarp();
                gemm2<DHD, 3, DHD, 0, DD>(sh_o, P.wo + layer * INNERD * DD + head * DHD * DD, DD,
                    [&](int pr, int o, float2 v) {
                        int j = o >> 5, i = pr & 3;
                        accw[i][j].x += v.x; accw[i][j].y += v.y;
                    });
                __syncwarp();
            }
            const float* bo = P.bo + layer * DD;
#pragma unroll
            for (int i = 0; i < 4; i++)
#pragma unroll
                for (int j = 0; j < 3; j++) {
                    int o = l + 32 * j;
                    if (o < DD) {
                        int pr = wp * 4 + i;
                        float2* addr = reinterpret_cast<float2*>(&sh_h[pr * 2 * LDH + 2 * o]);
                        float2 h = *addr;
                        float bb = bo[o];
                        h.x += accw[i][j].x + bb;
                        h.y += accw[i][j].y + bb;
                        *addr = h;
                    }
                }
            __syncwarp();
        }
        // ---- LN2 + MLP ----
        ln_warp(sh_h, sh_hn, P.ln2w + layer * DD, P.ln2b + layer * DD);
        {
            float2 accm[4][3];
#pragma unroll
            for (int i = 0; i < 4; i++)
#pragma unroll
                for (int j = 0; j < 3; j++) accm[i][j] = make_float2(0.f, 0.f);
            for (int c = 0; c < MLPD / 128; c++) {
                const float* b1c = P.b1 + layer * MLPD + c * 128;
                gemm2<DD, 4, LDH, 1, 128>(sh_hn, P.w1 + layer * DD * MLPD + c * 128, MLPD,
                    [&](int pr, int o, float2 v) {
                        float bb = b1c[o];
                        float x0 = v.x + bb, x1 = v.y + bb;
                        v.x = 0.5f * x0 * (1.0f + erff(x0 * 0.70710678118654752f));
                        v.y = 0.5f * x1 * (1.0f + erff(x1 * 0.70710678118654752f));
                        *reinterpret_cast<float2*>(&sh_s[pr * 2 * LDSS + 2 * o]) = v;
                    });
                __syncwarp();
                gemm2<128, 3, LDSS, 0, DD>(sh_s, P.w2 + layer * MLPD * DD + c * 128 * DD, DD,
                    [&](int pr, int o, float2 v) {
                        int j = o >> 5, i = pr & 3;
                        accm[i][j].x += v.x; accm[i][j].y += v.y;
                    });
                __syncwarp();
            }
            const float* b2 = P.b2 + layer * DD;
#pragma unroll
            for (int i = 0; i < 4; i++)
#pragma unroll
                for (int j = 0; j < 3; j++) {
                    int o = l + 32 * j;
                    if (o < DD) {
                        int pr = wp * 4 + i;
                        float2* addr = reinterpret_cast<float2*>(&sh_h[pr * 2 * LDH + 2 * o]);
                        float2 h = *addr;
                        float bb = b2[o];
                        h.x += accm[i][j].x + bb;
                        h.y += accm[i][j].y + bb;
                        *addr = h;
                    }
                }
            __syncwarp();
        }
    }

    // ---- density head ----
    gemm2<DD, 4, LDH, 1, 128>(sh_h, P.wd1, 128,
        [&](int pr, int o, float2 v) {
            float bb = P.bd1[o];
            v.x = fmaxf(v.x + bb, 0.f); v.y = fmaxf(v.y + bb, 0.f);
            *reinterpret_cast<float2*>(&sh_s[pr * 2 * LDSS + 2 * o]) = v;
        });
    __syncwarp();
    {
        const int pt = wp * 8 + pl;
        const float* rowb = sh_s + ((pt >> 1) * 2 * LDSS + (pt & 1));
        float a = 0.f;
#pragma unroll
        for (int k = 0; k < 32; k++) a = fmaf(rowb[2 * (sub + 4 * k)], P.wd2[sub + 4 * k], a);
        a += __shfl_xor_sync(0xffffffffu, a, 1);
        a += __shfl_xor_sync(0xffffffffu, a, 2);
        if (sub == 0) {
            a += P.bd2[0];
            float sp = fmaxf(a, 0.f) + log1pf(expf(-fabsf(a)));
            float* dst = mode ? g_dens_f : g_dens_c;
            dst[base + pt] = sp;
        }
    }
    __syncwarp();
    // ---- color head ----
    gemm2<DD, 4, LDH, 1, 128>(sh_h, P.wc1, 128,
        [&](int pr, int o, float2 v) {
            float bb = P.bc1[o];
            v.x = fmaxf(v.x + bb, 0.f); v.y = fmaxf(v.y + bb, 0.f);
            *reinterpret_cast<float2*>(&sh_s[pr * 2 * LDSS + 2 * o]) = v;
        });
    __syncwarp();
    {
        const int pt = wp * 8 + pl;
        const float* rowb = sh_s + ((pt >> 1) * 2 * LDSS + (pt & 1));
        float c0 = 0.f, c1 = 0.f, c2 = 0.f;
#pragma unroll
        for (int k = 0; k < 32; k++) {
            float v = rowb[2 * (sub + 4 * k)];
            const float* wr = P.wc2 + (sub + 4 * k) * 3;
            c0 = fmaf(v, wr[0], c0);
            c1 = fmaf(v, wr[1], c1);
            c2 = fmaf(v, wr[2], c2);
        }
        c0 += __shfl_xor_sync(0xffffffffu, c0, 1);
        c0 += __shfl_xor_sync(0xffffffffu, c0, 2);
        c1 += __shfl_xor_sync(0xffffffffu, c1, 1);
        c1 += __shfl_xor_sync(0xffffffffu, c1, 2);
        c2 += __shfl_xor_sync(0xffffffffu, c2, 1);
        c2 += __shfl_xor_sync(0xffffffffu, c2, 2);
        if (sub == 0) {
            int gp = base + pt;
            float* dst = mode ? g_col_f : g_col_c;
            dst[gp * 3 + 0] = 1.0f / (1.0f + expf(-(c0 + P.bc2[0])));
            dst[gp * 3 + 1] = 1.0f / (1.0f + expf(-(c1 + P.bc2[1])));
            dst[gp * 3 + 2] = 1.0f / (1.0f + expf(-(c2 + P.bc2[2])));
        }
    }
}

// ---------------- coarse render + PDF resampling + merge ----------------
__global__ void coarse_post_kernel(float* __restrict__ out) {
    int r = blockIdx.x * blockDim.x + threadIdx.x;
    if (r >= RAYS) return;
    float cd[NCO];
    for (int s = 0; s < NCO; s++) cd[s] = coarse_depth(s);

    float w[NCO];
    float T = 1.f, acc = 0.f, rgb0 = 0.f, rgb1 = 0.f, rgb2 = 0.f, dsum = 0.f;
    for (int s = 0; s < NCO; s++) {
        float seg = (s < NCO - 1) ? cd[s + 1] - cd[s] : 1e10f;
        float dens = g_dens_c[r * NCO + s];
        float alpha = 1.0f - expf(-dens * seg);
        float wi = alpha * T;
        w[s] = wi;
        T *= (1.0f - alpha + 1e-10f);
        acc += wi;
        rgb0 += wi * g_col_c[(r * NCO + s) * 3 + 0];
        rgb1 += wi * g_col_c[(r * NCO + s) * 3 + 1];
        rgb2 += wi * g_col_c[(r * NCO + s) * 3 + 2];
        dsum += wi * cd[s];
    }
    float inv = 1.0f / (acc + 1e-8f);
    out[3072 + r * 3 + 0] = 1.0f - acc + (rgb0 * inv) * acc;
    out[3072 + r * 3 + 1] = 1.0f - acc + (rgb1 * inv) * acc;
    out[3072 + r * 3 + 2] = 1.0f - acc + (rgb2 * inv) * acc;
    out[7168 + r] = dsum * inv;

    float bins[63], cdf[63];
    for (int i = 0; i < 63; i++) bins[i] = 0.5f * (cd[i] + cd[i + 1]);
    float wsum = 0.f;
    for (int i = 0; i < 62; i++) wsum += w[i + 1] + 1e-5f;
    cdf[0] = 0.f;
    float c0 = 0.f;
    for (int i = 0; i < 62; i++) { c0 += (w[i + 1] + 1e-5f) / wsum; cdf[i + 1] = c0; }

    float fd[NFI];
    for (int j = 0; j < NFI; j++) {
        float u = (j + 0.5f) * (1.0f / NFI);
        int ind = 0;
        for (int k = 0; k < 63; k++) if (cdf[k] <= u) ind = k + 1;
        int below = ind - 1; if (below < 0) below = 0; if (below > 62) below = 62;
        int above = ind;     if (above > 62) above = 62;
        float cb = cdf[below], ca = cdf[above];
        float bb = bins[below], ba = bins[above];
        float denom = ca - cb;
        if (denom < 1e-5f) denom = 1.0f;
        fd[j] = bb + (u - cb) / denom * (ba - bb);
    }
    int i = 0, j = 0;
    for (int k = 0; k < NAGG; k++) {
        float v;
        if (j >= NFI || (i < NCO && cd[i] <= fd[j])) v = cd[i++];
        else v = fd[j++];
        g_depths[r * NAGG + k] = v;
    }
}

// ---------------- fine render ----------------
__global__ void fine_post_kernel(float* __restrict__ out) {
    int r = blockIdx.x * blockDim.x + threadIdx.x;
    if (r >= RAYS) return;
    float d[NAGG];
    for (int s = 0; s < NAGG; s++) d[s] = g_depths[r * NAGG + s];
    float T = 1.f, acc = 0.f, rgb0 = 0.f, rgb1 = 0.f, rgb2 = 0.f, dsum = 0.f;
    for (int s = 0; s < NAGG; s++) {
        float seg = (s < NAGG - 1) ? d[s + 1] - d[s] : 1e10f;
        float dens = g_dens_f[r * NAGG + s];
        float alpha = 1.0f - expf(-dens * seg);
        float wi = alpha * T;
        T *= (1.0f - alpha + 1e-10f);
        acc += wi;
        rgb0 += wi * g_col_f[(r * NAGG + s) * 3 + 0];
        rgb1 += wi * g_col_f[(r * NAGG + s) * 3 + 1];
        rgb2 += wi * g_col_f[(r * NAGG + s) * 3 + 2];
        dsum += wi * d[s];
    }
    float inv = 1.0f / (acc + 1e-8f);
    out[r * 3 + 0] = 1.0f - acc + (rgb0 * inv) * acc;
    out[r * 3 + 1] = 1.0f - acc + (rgb1 * inv) * acc;
    out[r * 3 + 2] = 1.0f - acc + (rgb2 * inv) * acc;
    out[6144 + r] = dsum * inv;
}

// ---------------- launch ----------------
extern "C" void kernel_launch(void* const* d_in, const int* in_sizes, int n_in,
                              void* d_out, int out_size) {
    const float* z    = (const float*)d_in[0];
    NetP P;
    P.x    = (const float*)d_in[1];
    P.rays = (const float*)d_in[2];
    P.ln1w = (const float*)d_in[3];
    P.ln1b = (const float*)d_in[4];
    P.wq   = (const float*)d_in[5];
    const float* wkv = (const float*)d_in[6];
    P.wo   = (const float*)d_in[7];
    P.bo   = (const float*)d_in[8];
    P.ln2w = (const float*)d_in[9];
    P.ln2b = (const float*)d_in[10];
    P.w1   = (const float*)d_in[11];
    P.b1   = (const float*)d_in[12];
    P.w2   = (const float*)d_in[13];
    P.b2   = (const float*)d_in[14];
    P.wc1  = (const float*)d_in[15];
    P.bc1  = (const float*)d_in[16];
    P.wc2  = (const float*)d_in[17];
    P.bc2  = (const float*)d_in[18];
    P.wd1  = (const float*)d_in[19];
    P.bd1  = (const float*)d_in[20];
    P.wd2  = (const float*)d_in[21];
    P.bd2  = (const float*)d_in[22];
    float* out = (float*)d_out;

    kv_kernel<<<(2 * PTOK * 2 * INNERD + 255) / 256, 256>>>(z, wkv);
    net_kernel<<<(RAYS * NCO) / PPB, 64>>>(P, 0);
    coarse_post_kernel<<<(RAYS + 127) / 128, 128>>>(out);
    net_kernel<<<(RAYS * NAGG) / PPB, 64>>>(P, 1);
    fine_post_kernel<<<(RAYS + 127) / 128, 128>>>(out);
}